// round 6
// baseline (speedup 1.0000x reference)
#include <cuda_runtime.h>
#include <cstdint>

// Sepconv: out[b,c,y,x] = sum_{i,j} in[b,c,5y+i,5x+j] * V[b,i,y,x] * H[b,j,y,x]
// B=8, C=3, F=5, HO=WO=256. HBM-bound (~184 MB compulsory traffic).
//
// R6: persistent blocks + continuous depth-4 cp.async ring.
// 608 blocks (one wave, ~4/SM), each grid-strides over (b,y,half) tiles.
// The ring of 4 channel-strip buffers is kept full across tile boundaries,
// so a block's DRAM request stream never drains until its final strip.

#define B_ 8
#define C_ 3
#define F_ 5
#define HO_ 256
#define WO_ 256
#define HI_ (HO_ * F_)
#define WI_ (WO_ * F_)

#define HALF_W   (WO_ / 2)               // 128 outputs per tile
#define STRIP_W  (HALF_W * F_)           // 640 floats per input row chunk
#define TILE_FLOATS (F_ * STRIP_W)       // 3200 floats = 12.8 KB per strip
#define TILE_VEC4   (TILE_FLOATS / 4)    // 800 float4
#define NT 128
#define NBUF 4
#define FULL_PASSES (TILE_VEC4 / NT)     // 6
#define REM_VEC4    (TILE_VEC4 - FULL_PASSES * NT)  // 32

#define NTILES   (B_ * HO_ * 2)          // 4096
#define GRID_    608                     // ~4 blocks/SM on 152 SMs, one wave

__device__ __forceinline__ void cp16(uint32_t dst_smem, const float4* src) {
    asm volatile("cp.async.cg.shared.global [%0], [%1], 16;\n"
                 :: "r"(dst_smem), "l"(src));
}
__device__ __forceinline__ void cp_commit() {
    asm volatile("cp.async.commit_group;\n");
}
template <int N>
__device__ __forceinline__ void cp_wait() {
    asm volatile("cp.async.wait_group %0;\n" :: "n"(N));
}

__global__ __launch_bounds__(NT) void sepconv_persist_kernel(
    const float* __restrict__ in,
    const float* __restrict__ V,
    const float* __restrict__ H,
    float* __restrict__ out)
{
    extern __shared__ float smem[];      // NBUF * TILE_FLOATS = 51.2 KB

    const int tid = threadIdx.x;
    const int bid = blockIdx.x;

    const uint32_t sbase_u = (uint32_t)__cvta_generic_to_shared(smem);

    const int ntiles  = (NTILES - bid + GRID_ - 1) / GRID_;
    const int nstrips = ntiles * C_;

    // Issue strip s (= tile-slot k, channel c) into ring buffer s % NBUF.
    auto issue = [&](int s) {
        const int k = s / C_;
        const int c = s % C_;
        const int t = bid + k * GRID_;           // tile id < NTILES guaranteed
        const int half = t & 1;
        const int y    = (t >> 1) & (HO_ - 1);
        const int b    = t >> 9;
        const float* strip = in
            + ((long long)((b * C_ + c) * HI_ + y * F_)) * WI_
            + (long long)(half * STRIP_W);
        uint32_t dst = sbase_u + (uint32_t)((s % NBUF) * TILE_FLOATS) * 4u;
#pragma unroll
        for (int p = 0; p < FULL_PASSES; p++) {
            int idx = tid + p * NT;              // 0..767
            int row = idx / (STRIP_W / 4);
            int col = idx % (STRIP_W / 4);
            cp16(dst + (uint32_t)idx * 16u,
                 reinterpret_cast<const float4*>(strip + row * WI_) + col);
        }
        if (tid < REM_VEC4) {
            int idx = tid + FULL_PASSES * NT;    // 768..799
            int row = idx / (STRIP_W / 4);
            int col = idx % (STRIP_W / 4);
            cp16(dst + (uint32_t)idx * 16u,
                 reinterpret_cast<const float4*>(strip + row * WI_) + col);
        }
        cp_commit();
    };

    // Prologue: fill the ring.
    int issued = 0;
    const int pro = nstrips < NBUF ? nstrips : NBUF;
    for (; issued < pro; issued++) issue(issued);

    float v[F_], h[F_];   // weights for the current tile (refreshed at c==0)

    for (int s = 0; s < nstrips; s++) {
        const int k = s / C_;
        const int c = s % C_;
        const int t = bid + k * GRID_;
        const int half = t & 1;
        const int y    = (t >> 1) & (HO_ - 1);
        const int b    = t >> 9;
        const int x0   = half * HALF_W;

        if (c == 0) {
            const int sb = (b * F_) * (HO_ * WO_) + y * WO_ + x0 + tid;
#pragma unroll
            for (int i = 0; i < F_; i++) {
                v[i] = V[sb + i * (HO_ * WO_)];
                h[i] = H[sb + i * (HO_ * WO_)];
            }
        }

        // Wait until strip s's group is complete: pending <= issued - s - 1.
        const int pend = issued - s - 1;         // 0..3
        switch (pend) {
            case 3: cp_wait<3>(); break;
            case 2: cp_wait<2>(); break;
            case 1: cp_wait<1>(); break;
            default: cp_wait<0>(); break;
        }
        __syncthreads();

        const float* sb2 = smem + (s % NBUF) * TILE_FLOATS;
        float acc = 0.0f;
#pragma unroll
        for (int i = 0; i < F_; i++) {
            const float* row = sb2 + i * STRIP_W + tid * F_;
            float rs = 0.0f;
#pragma unroll
            for (int j = 0; j < F_; j++)
                rs = fmaf(row[j], h[j], rs);
            acc = fmaf(rs, v[i], acc);
        }
        __stcs(out + ((b * C_ + c) * HO_ + y) * WO_ + x0 + tid, acc);

        __syncthreads();                          // buffer free for reuse
        if (issued < nstrips) { issue(issued); issued++; }
    }
}

extern "C" void kernel_launch(void* const* d_in, const int* in_sizes, int n_in,
                              void* d_out, int out_size)
{
    const float* in  = (const float*)d_in[0];  // [8,3,1280,1280]
    const float* V   = (const float*)d_in[1];  // [8,5,256,256]
    const float* H   = (const float*)d_in[2];  // [8,5,256,256]
    float* out = (float*)d_out;                // [8,3,256,256]

    const int smem_bytes = NBUF * TILE_FLOATS * (int)sizeof(float);  // 51200
    cudaFuncSetAttribute(sepconv_persist_kernel,
                         cudaFuncAttributeMaxDynamicSharedMemorySize,
                         smem_bytes);

    sepconv_persist_kernel<<<GRID_, NT, smem_bytes>>>(in, V, H, out);
}

// round 7
// speedup vs baseline: 1.0183x; 1.0183x over previous
#include <cuda_runtime.h>
#include <cstdint>

// Sepconv: out[b,c,y,x] = sum_{i,j} in[b,c,5y+i,5x+j] * V[b,i,y,x] * H[b,j,y,x]
// B=8, C=3, F=5, HO=WO=256. HBM-bound (~184 MB compulsory).
//
// R7: warp-specialized producer/consumer with an mbarrier'd cp.async ring.
// Block = 160 threads: warps 0-3 consume, warp 4 produces. Producer streams
// 12.8KB channel-strips through a 4-buffer ring gated only by empty-barrier
// backpressure -> the global-load stream never waits on compute. Persistent
// grid of 608 blocks (one wave, 4 blocks/SM).

#define B_ 8
#define C_ 3
#define F_ 5
#define HO_ 256
#define WO_ 256
#define HI_ (HO_ * F_)
#define WI_ (WO_ * F_)

#define HALF_W   128
#define STRIP_W  (HALF_W * F_)            // 640 floats per row chunk
#define STRIP_V4 (STRIP_W / 4)            // 160
#define TILE_FLOATS (F_ * STRIP_W)        // 3200 floats = 12.8 KB
#define TILE_V4     (TILE_FLOATS / 4)     // 800
#define NBUF 4
#define NCONS 128
#define NT 160
#define NTILES (B_ * HO_ * 2)             // 4096
#define GRID_  608

__device__ __forceinline__ void cp16(uint32_t dst_smem, const float4* src) {
    asm volatile("cp.async.cg.shared.global [%0], [%1], 16;\n"
                 :: "r"(dst_smem), "l"(src));
}
__device__ __forceinline__ void mbar_init(uint32_t mbar, uint32_t count) {
    asm volatile("mbarrier.init.shared.b64 [%0], %1;\n"
                 :: "r"(mbar), "r"(count) : "memory");
}
__device__ __forceinline__ void mbar_arrive(uint32_t mbar) {
    asm volatile("mbarrier.arrive.shared.b64 _, [%0];\n"
                 :: "r"(mbar) : "memory");
}
// Arrive on mbar when all of this thread's prior cp.asyncs have completed.
__device__ __forceinline__ void cp_arrive_noinc(uint32_t mbar) {
    asm volatile("cp.async.mbarrier.arrive.noinc.shared.b64 [%0];\n"
                 :: "r"(mbar) : "memory");
}
// Blocks while the barrier's current phase parity == parity.
__device__ __forceinline__ void mbar_wait(uint32_t mbar, uint32_t parity) {
    asm volatile(
        "{\n\t"
        ".reg .pred P;\n\t"
        "WAIT_%=:\n\t"
        "mbarrier.try_wait.parity.acquire.cta.shared::cta.b64 P, [%0], %1, 0x989680;\n\t"
        "@!P bra WAIT_%=;\n\t"
        "}"
        :: "r"(mbar), "r"(parity) : "memory");
}

__global__ __launch_bounds__(NT) void sepconv_ws_kernel(
    const float* __restrict__ in,
    const float* __restrict__ V,
    const float* __restrict__ H,
    float* __restrict__ out)
{
    extern __shared__ float sdata[];                      // NBUF * TILE_FLOATS
    __shared__ __align__(8) unsigned long long full_b[NBUF];
    __shared__ __align__(8) unsigned long long empty_b[NBUF];

    const int tid = threadIdx.x;
    const int bid = blockIdx.x;

    const uint32_t sdata_u = (uint32_t)__cvta_generic_to_shared(sdata);
    const uint32_t full_u  = (uint32_t)__cvta_generic_to_shared(full_b);
    const uint32_t empty_u = (uint32_t)__cvta_generic_to_shared(empty_b);

    if (tid == 0) {
#pragma unroll
        for (int i = 0; i < NBUF; i++) {
            mbar_init(full_u  + 8u * i, 32);     // producer lanes
            mbar_init(empty_u + 8u * i, NCONS);  // consumer threads
        }
    }
    __syncthreads();

    const int cnt     = (NTILES - bid + GRID_ - 1) / GRID_;   // 6 or 7 tiles
    const int nstrips = cnt * C_;

    if (tid >= NCONS) {
        // ---------------- producer warp ----------------
        const int lane = tid - NCONS;                     // 0..31
        for (int s = 0; s < nstrips; s++) {
            const int buf = s & (NBUF - 1);
            const uint32_t ph = (((uint32_t)s >> 2) & 1u) ^ 1u;
            mbar_wait(empty_u + 8u * buf, ph);            // backpressure

            const int kk = s / C_;
            const int c  = s - kk * C_;
            const int t  = bid + kk * GRID_;
            const int half = t & 1;
            const int y    = (t >> 1) & (HO_ - 1);
            const int b    = t >> 9;
            const float* strip = in
                + ((long long)((b * C_ + c) * HI_ + y * F_)) * WI_
                + (long long)(half * STRIP_W);
            const uint32_t dst = sdata_u + (uint32_t)(buf * TILE_FLOATS) * 4u;
#pragma unroll
            for (int l = 0; l < TILE_V4 / 32; l++) {      // 25 cp16 per lane
                const int idx = lane + l * 32;
                const int row = idx / STRIP_V4;
                const int col = idx - row * STRIP_V4;
                cp16(dst + (uint32_t)idx * 16u,
                     reinterpret_cast<const float4*>(strip + row * WI_) + col);
            }
            cp_arrive_noinc(full_u + 8u * buf);           // data-ready signal
        }
    } else {
        // ---------------- consumer warps ----------------
        float v[F_], h[F_];
        for (int s = 0; s < nstrips; s++) {
            const int buf = s & (NBUF - 1);
            const uint32_t ph = ((uint32_t)s >> 2) & 1u;

            const int kk = s / C_;
            const int c  = s - kk * C_;
            const int t  = bid + kk * GRID_;
            const int half = t & 1;
            const int y    = (t >> 1) & (HO_ - 1);
            const int b    = t >> 9;
            const int x0   = half * HALF_W;

            if (c == 0) {                                 // new tile weights
                const int sb = (b * F_) * (HO_ * WO_) + y * WO_ + x0 + tid;
#pragma unroll
                for (int i = 0; i < F_; i++) {
                    v[i] = V[sb + i * (HO_ * WO_)];
                    h[i] = H[sb + i * (HO_ * WO_)];
                }
            }

            mbar_wait(full_u + 8u * buf, ph);             // data ready (acquire)

            const float* sb2 = sdata + buf * TILE_FLOATS;
            float acc = 0.0f;
#pragma unroll
            for (int i = 0; i < F_; i++) {
                const float* row = sb2 + i * STRIP_W + tid * F_;
                float rs = 0.0f;
#pragma unroll
                for (int j = 0; j < F_; j++)
                    rs = fmaf(row[j], h[j], rs);
                acc = fmaf(rs, v[i], acc);
            }
            __stcs(out + ((b * C_ + c) * HO_ + y) * WO_ + x0 + tid, acc);

            mbar_arrive(empty_u + 8u * buf);              // recycle buffer
        }
    }
}

extern "C" void kernel_launch(void* const* d_in, const int* in_sizes, int n_in,
                              void* d_out, int out_size)
{
    const float* in  = (const float*)d_in[0];  // [8,3,1280,1280]
    const float* V   = (const float*)d_in[1];  // [8,5,256,256]
    const float* H   = (const float*)d_in[2];  // [8,5,256,256]
    float* out = (float*)d_out;                // [8,3,256,256]

    const int smem_bytes = NBUF * TILE_FLOATS * (int)sizeof(float);  // 51200
    cudaFuncSetAttribute(sepconv_ws_kernel,
                         cudaFuncAttributeMaxDynamicSharedMemorySize,
                         smem_bytes);

    sepconv_ws_kernel<<<GRID_, NT, smem_bytes>>>(in, V, H, out);
}

// round 8
// speedup vs baseline: 1.0516x; 1.0328x over previous
#include <cuda_runtime.h>
#include <cstdint>

// Sepconv: out[b,c,y,x] = sum_{i,j} in[b,c,5y+i,5x+j] * V[b,i,y,x] * H[b,j,y,x]
// B=8, C=3, F=5, HO=WO=256. HBM-bound (~184 MB compulsory).
//
// R8: R5's schedule (4096 blocks x 128 threads, all 3 channel strips posted
// up-front) but loads go through cp.async.bulk (TMA/UBLKCP): 5 copies of
// 2560 contiguous bytes per strip, completing on per-channel mbarriers with
// expect_tx. The memory controller sees 2.5KB sequential extents instead of
// per-thread 16B requests -> better DRAM row-buffer efficiency.

#define B_ 8
#define C_ 3
#define F_ 5
#define HO_ 256
#define WO_ 256
#define HI_ (HO_ * F_)
#define WI_ (WO_ * F_)

#define HALF_W   128
#define STRIP_W  (HALF_W * F_)            // 640 floats per row chunk
#define ROW_BYTES (STRIP_W * 4)           // 2560 B per bulk copy
#define TILE_FLOATS (F_ * STRIP_W)        // 3200 floats = 12.8 KB per strip
#define TILE_BYTES  (TILE_FLOATS * 4)     // 12800
#define NT 128

__device__ __forceinline__ void mbar_init(uint32_t mbar, uint32_t count) {
    asm volatile("mbarrier.init.shared.b64 [%0], %1;\n"
                 :: "r"(mbar), "r"(count) : "memory");
}
__device__ __forceinline__ void mbar_expect_tx(uint32_t mbar, uint32_t bytes) {
    asm volatile("mbarrier.arrive.expect_tx.shared.b64 _, [%0], %1;\n"
                 :: "r"(mbar), "r"(bytes) : "memory");
}
__device__ __forceinline__ void bulk_cp(uint32_t dst, const void* src,
                                        uint32_t bytes, uint32_t mbar) {
    asm volatile(
        "cp.async.bulk.shared::cta.global.mbarrier::complete_tx::bytes "
        "[%0], [%1], %2, [%3];\n"
        :: "r"(dst), "l"(src), "r"(bytes), "r"(mbar) : "memory");
}
__device__ __forceinline__ void mbar_wait(uint32_t mbar, uint32_t parity) {
    asm volatile(
        "{\n\t"
        ".reg .pred P;\n\t"
        "WAIT_%=:\n\t"
        "mbarrier.try_wait.parity.acquire.cta.shared::cta.b64 P, [%0], %1, 0x989680;\n\t"
        "@!P bra WAIT_%=;\n\t"
        "}"
        :: "r"(mbar), "r"(parity) : "memory");
}

__global__ __launch_bounds__(NT) void sepconv_tma_kernel(
    const float* __restrict__ in,
    const float* __restrict__ V,
    const float* __restrict__ H,
    float* __restrict__ out)
{
    __shared__ __align__(16) float sdata[C_ * TILE_FLOATS];   // 38.4 KB
    __shared__ __align__(8) unsigned long long mbar[C_];

    const int tid  = threadIdx.x;        // 0..127
    const int half = blockIdx.x & 1;
    const int y    = (blockIdx.x >> 1) & (HO_ - 1);
    const int b    = blockIdx.x >> 9;
    const int x0   = half * HALF_W;

    const uint32_t sdata_u = (uint32_t)__cvta_generic_to_shared(sdata);
    const uint32_t mbar_u  = (uint32_t)__cvta_generic_to_shared(mbar);

    if (tid == 0) {
#pragma unroll
        for (int c = 0; c < C_; c++)
            mbar_init(mbar_u + 8u * c, 1);
        // Make generic-proxy mbarrier init visible to the async proxy.
        asm volatile("fence.proxy.async.shared::cta;\n" ::: "memory");
    }
    __syncthreads();

    // Post all 15 bulk copies (3 channels x 5 rows) up-front from one thread.
    if (tid == 0) {
        const long long base0 = ((long long)(b * C_) * HI_ + (long long)y * F_) * WI_
                                + (long long)half * STRIP_W;
#pragma unroll
        for (int c = 0; c < C_; c++) {
            mbar_expect_tx(mbar_u + 8u * c, TILE_BYTES);
            const float* strip = in + base0 + (long long)c * HI_ * WI_;
            const uint32_t dst = sdata_u + (uint32_t)(c * TILE_BYTES);
#pragma unroll
            for (int r = 0; r < F_; r++)
                bulk_cp(dst + (uint32_t)(r * ROW_BYTES),
                        strip + r * WI_, ROW_BYTES, mbar_u + 8u * c);
        }
    }

    // Weights for (b, y, x0+tid): coalesced, overlap with TMA in flight.
    float v[F_], h[F_];
    {
        const int sb = (b * F_) * (HO_ * WO_) + y * WO_ + x0 + tid;
#pragma unroll
        for (int i = 0; i < F_; i++) {
            v[i] = V[sb + i * (HO_ * WO_)];
            h[i] = H[sb + i * (HO_ * WO_)];
        }
    }

#pragma unroll
    for (int c = 0; c < C_; c++) {
        mbar_wait(mbar_u + 8u * c, 0);            // acquire: strip c ready

        const float* s = sdata + c * TILE_FLOATS;
        float acc = 0.0f;
#pragma unroll
        for (int i = 0; i < F_; i++) {
            const float* row = s + i * STRIP_W + tid * F_;
            float rs = 0.0f;
#pragma unroll
            for (int j = 0; j < F_; j++)
                rs = fmaf(row[j], h[j], rs);
            acc = fmaf(rs, v[i], acc);
        }
        __stcs(out + ((b * C_ + c) * HO_ + y) * WO_ + x0 + tid, acc);
    }
}

extern "C" void kernel_launch(void* const* d_in, const int* in_sizes, int n_in,
                              void* d_out, int out_size)
{
    const float* in  = (const float*)d_in[0];  // [8,3,1280,1280]
    const float* V   = (const float*)d_in[1];  // [8,5,256,256]
    const float* H   = (const float*)d_in[2];  // [8,5,256,256]
    float* out = (float*)d_out;                // [8,3,256,256]

    const int blocks = B_ * HO_ * 2;           // 4096: (b, y, half)
    sepconv_tma_kernel<<<blocks, NT>>>(in, V, H, out);
}